// round 4
// baseline (speedup 1.0000x reference)
#include <cuda_runtime.h>
#include <math.h>

// Problem constants
#define BB 4
#define SS 1024
#define DD 1024
#define HH 16
#define DHH 64
#define MSZ (BB * SS)  // 4096 rows

// Scratch (no cudaMalloc allowed)
__device__ float g_Q[(size_t)MSZ * DD];
__device__ float g_K[(size_t)MSZ * DD];
__device__ float g_V[(size_t)MSZ * DD];
__device__ float g_C[(size_t)MSZ * DD];
__device__ unsigned char g_mask[BB * SS];

// ----------------------------------------------------------------------------
// Mask canonicalization: detect dtype (uint8 / float32 / int32) from byte
// signature, then write combined mask|semask as uint8.
// ----------------------------------------------------------------------------
__global__ __launch_bounds__(1024) void mask_prep_kernel(
    const unsigned char* __restrict__ m0,
    const unsigned char* __restrict__ m1)
{
    __shared__ int s_flags;
    const int t = threadIdx.x;
    if (t == 0) s_flags = 0;
    __syncthreads();

    // First 4096 bytes are valid for every candidate dtype
    // (uint8: whole buffer; int32/float32: first 1024 elements).
    int f1 = 0, f23 = 0;
    for (int i = t; i < BB * SS; i += 1024) {
        unsigned char a = (unsigned char)(m0[i] | m1[i]);
        int r = i & 3;
        if (a) {
            if (r == 1) f1 = 1;
            else if (r >= 2) f23 = 1;
        }
    }
    if (f1)  atomicOr(&s_flags, 1);
    if (f23) atomicOr(&s_flags, 2);
    __syncthreads();

    const int fl = s_flags;
    // uint8: nonzero bytes appear at idx%4==1 (10% mask density -> w.h.p.)
    // float32 (0.0/1.0): nonzero bytes only at idx%4==2,3 (0x80, 0x3F)
    // int32 (0/1): nonzero bytes only at idx%4==0
    int code;
    if (fl & 1)      code = 0;  // uint8
    else if (fl & 2) code = 1;  // float32
    else             code = 2;  // int32 (or all-zero: any decode works)

    for (int i = t; i < BB * SS; i += 1024) {
        unsigned char mm;
        if (code == 0) {
            mm = (unsigned char)((m0[i] != 0) | (m1[i] != 0));
        } else if (code == 1) {
            mm = (unsigned char)((((const float*)m0)[i] != 0.f) |
                                 (((const float*)m1)[i] != 0.f));
        } else {
            mm = (unsigned char)((((const int*)m0)[i] != 0) |
                                 (((const int*)m1)[i] != 0));
        }
        g_mask[i] = mm;
    }
}

// ----------------------------------------------------------------------------
// SGEMM: C[M,N] = A[M,K] @ W[N,K]^T + bias[N]
// Tiles: 128x128x16, 256 threads, 8x8 per-thread micro-tile.
// ----------------------------------------------------------------------------
__global__ __launch_bounds__(256) void sgemm_bt_kernel(
    const float* __restrict__ A, const float* __restrict__ W,
    const float* __restrict__ bias, float* __restrict__ C,
    int M, int N, int K)
{
    __shared__ float As[16][128];
    __shared__ float Bs[16][128];

    const int tid = threadIdx.x;
    const int bm = blockIdx.y * 128;
    const int bn = blockIdx.x * 128;
    const int tx = tid & 15;
    const int ty = tid >> 4;
    const int lr = tid >> 2;
    const int lc = (tid & 3) << 2;

    float acc[8][8];
#pragma unroll
    for (int i = 0; i < 8; i++)
#pragma unroll
        for (int j = 0; j < 8; j++) acc[i][j] = 0.f;

    const float* Ar0 = A + (size_t)(bm + lr) * K + lc;
    const float* Ar1 = Ar0 + (size_t)64 * K;
    const float* Wr0 = W + (size_t)(bn + lr) * K + lc;
    const float* Wr1 = Wr0 + (size_t)64 * K;

    for (int k0 = 0; k0 < K; k0 += 16) {
        float4 a0 = *(const float4*)(Ar0 + k0);
        float4 a1 = *(const float4*)(Ar1 + k0);
        float4 w0 = *(const float4*)(Wr0 + k0);
        float4 w1 = *(const float4*)(Wr1 + k0);

        __syncthreads();
        As[lc + 0][lr] = a0.x; As[lc + 1][lr] = a0.y;
        As[lc + 2][lr] = a0.z; As[lc + 3][lr] = a0.w;
        As[lc + 0][lr + 64] = a1.x; As[lc + 1][lr + 64] = a1.y;
        As[lc + 2][lr + 64] = a1.z; As[lc + 3][lr + 64] = a1.w;
        Bs[lc + 0][lr] = w0.x; Bs[lc + 1][lr] = w0.y;
        Bs[lc + 2][lr] = w0.z; Bs[lc + 3][lr] = w0.w;
        Bs[lc + 0][lr + 64] = w1.x; Bs[lc + 1][lr + 64] = w1.y;
        Bs[lc + 2][lr + 64] = w1.z; Bs[lc + 3][lr + 64] = w1.w;
        __syncthreads();

#pragma unroll
        for (int kk = 0; kk < 16; kk++) {
            float4 a_0 = *(const float4*)&As[kk][ty * 8];
            float4 a_1 = *(const float4*)&As[kk][ty * 8 + 4];
            float4 b_0 = *(const float4*)&Bs[kk][tx * 8];
            float4 b_1 = *(const float4*)&Bs[kk][tx * 8 + 4];
            float ar[8] = {a_0.x, a_0.y, a_0.z, a_0.w, a_1.x, a_1.y, a_1.z, a_1.w};
            float br[8] = {b_0.x, b_0.y, b_0.z, b_0.w, b_1.x, b_1.y, b_1.z, b_1.w};
#pragma unroll
            for (int i = 0; i < 8; i++)
#pragma unroll
                for (int j = 0; j < 8; j++)
                    acc[i][j] = fmaf(ar[i], br[j], acc[i][j]);
        }
    }

    float bb[8];
#pragma unroll
    for (int j = 0; j < 8; j++) bb[j] = bias[bn + tx * 8 + j];
#pragma unroll
    for (int i = 0; i < 8; i++) {
        float* crow = C + (size_t)(bm + ty * 8 + i) * N + bn + tx * 8;
        float4 o0 = make_float4(acc[i][0] + bb[0], acc[i][1] + bb[1],
                                acc[i][2] + bb[2], acc[i][3] + bb[3]);
        float4 o1 = make_float4(acc[i][4] + bb[4], acc[i][5] + bb[5],
                                acc[i][6] + bb[6], acc[i][7] + bb[7]);
        *(float4*)crow = o0;
        *(float4*)(crow + 4) = o1;
    }
}

// ----------------------------------------------------------------------------
// Flash attention (fp32, online softmax). One thread = one query row.
// ----------------------------------------------------------------------------
__global__ __launch_bounds__(128) void attn_kernel()
{
    const int t = threadIdx.x;
    const int q = blockIdx.x * 128 + t;
    const int h = blockIdx.y;
    const int b = blockIdx.z;
    const int hoff = h * DHH;

    __shared__ float Ks[64][64];
    __shared__ float Vs[64][64];
    __shared__ unsigned char smask[64];

    const float* qptr = g_Q + (size_t)(b * SS + q) * DD + hoff;
    float4 qv[16];
#pragma unroll
    for (int i = 0; i < 16; i++) qv[i] = *(const float4*)&qptr[i * 4];

    float4 ov[16];
#pragma unroll
    for (int i = 0; i < 16; i++) ov[i] = make_float4(0.f, 0.f, 0.f, 0.f);
    float mrun = -INFINITY;
    float lrun = 0.f;
    const float scale = 0.125f;  // 1/sqrt(64)

    for (int k0 = 0; k0 < SS; k0 += 64) {
        __syncthreads();
#pragma unroll
        for (int i = 0; i < 8; i++) {
            int f = t + i * 128;
            int j = f >> 4;
            int c = (f & 15) << 2;
            size_t g = (size_t)(b * SS + k0 + j) * DD + hoff + c;
            *(float4*)&Ks[j][c] = *(const float4*)&g_K[g];
            *(float4*)&Vs[j][c] = *(const float4*)&g_V[g];
        }
        if (t < 64) smask[t] = g_mask[b * SS + k0 + t];
        __syncthreads();

#pragma unroll 4
        for (int j = 0; j < 64; j++) {
            const float4* kr = (const float4*)Ks[j];
            float s = 0.f;
#pragma unroll
            for (int i = 0; i < 16; i++) {
                float4 kv = kr[i];
                s = fmaf(qv[i].x, kv.x, s);
                s = fmaf(qv[i].y, kv.y, s);
                s = fmaf(qv[i].z, kv.z, s);
                s = fmaf(qv[i].w, kv.w, s);
            }
            s *= scale;
            if (smask[j]) s = -1e9f;

            float p;
            if (s <= mrun) {
                p = __expf(s - mrun);
            } else {
                float corr = __expf(mrun - s);
                lrun *= corr;
#pragma unroll
                for (int i = 0; i < 16; i++) {
                    ov[i].x *= corr; ov[i].y *= corr;
                    ov[i].z *= corr; ov[i].w *= corr;
                }
                mrun = s;
                p = 1.f;
            }
            lrun += p;

            const float4* vr = (const float4*)Vs[j];
#pragma unroll
            for (int i = 0; i < 16; i++) {
                float4 vv = vr[i];
                ov[i].x = fmaf(p, vv.x, ov[i].x);
                ov[i].y = fmaf(p, vv.y, ov[i].y);
                ov[i].z = fmaf(p, vv.z, ov[i].z);
                ov[i].w = fmaf(p, vv.w, ov[i].w);
            }
        }
    }

    const float inv = 1.f / lrun;
    float* optr = g_C + (size_t)(b * SS + q) * DD + hoff;
#pragma unroll
    for (int i = 0; i < 16; i++) {
        float4 o = make_float4(ov[i].x * inv, ov[i].y * inv,
                               ov[i].z * inv, ov[i].w * inv);
        *(float4*)&optr[i * 4] = o;
    }
}

// ----------------------------------------------------------------------------
// Launch
// ----------------------------------------------------------------------------
extern "C" void kernel_launch(void* const* d_in, const int* in_sizes, int n_in,
                              void* d_out, int out_size)
{
    const float* v = (const float*)d_in[0];
    const float* k = (const float*)d_in[1];
    const float* q = (const float*)d_in[2];
    const unsigned char* mask   = (const unsigned char*)d_in[3];
    const unsigned char* semask = (const unsigned char*)d_in[4];
    const float* Wv = (const float*)d_in[5];
    const float* bv = (const float*)d_in[6];
    const float* Wk = (const float*)d_in[7];
    const float* bk = (const float*)d_in[8];
    const float* Wq = (const float*)d_in[9];
    const float* bq = (const float*)d_in[10];
    const float* Wm = (const float*)d_in[11];
    const float* bm = (const float*)d_in[12];

    static float* Qp = nullptr;
    static float* Kp = nullptr;
    static float* Vp = nullptr;
    static float* Cp = nullptr;
    if (!Qp) {
        cudaGetSymbolAddress((void**)&Qp, g_Q);
        cudaGetSymbolAddress((void**)&Kp, g_K);
        cudaGetSymbolAddress((void**)&Vp, g_V);
        cudaGetSymbolAddress((void**)&Cp, g_C);
    }

    mask_prep_kernel<<<1, 1024>>>(mask, semask);

    dim3 ggrid(DD / 128, MSZ / 128);
    sgemm_bt_kernel<<<ggrid, 256>>>(v, Wv, bv, Vp, MSZ, DD, DD);
    sgemm_bt_kernel<<<ggrid, 256>>>(k, Wk, bk, Kp, MSZ, DD, DD);
    sgemm_bt_kernel<<<ggrid, 256>>>(q, Wq, bq, Qp, MSZ, DD, DD);

    dim3 agrid(SS / 128, HH, BB);
    attn_kernel<<<agrid, 128>>>();

    sgemm_bt_kernel<<<ggrid, 256>>>(Cp, Wm, bm, (float*)d_out, MSZ, DD, DD);
}

// round 5
// speedup vs baseline: 1.4224x; 1.4224x over previous
#include <cuda_runtime.h>
#include <cuda_bf16.h>
#include <math.h>

// Problem constants
#define BB 4
#define SS 1024
#define DD 1024
#define HH 16
#define DHH 64
#define MSZ (BB * SS)  // 4096 rows

// Scratch (no cudaMalloc allowed)
__device__ float g_Q[(size_t)MSZ * DD];
__device__ float g_K[(size_t)MSZ * DD];
__device__ float g_V[(size_t)MSZ * DD];
__device__ float g_C[(size_t)MSZ * DD];
__device__ unsigned char g_mask[BB * SS];

// ----------------------------------------------------------------------------
// Mask canonicalization (verified in R4): detect dtype (uint8/float32/int32)
// by byte signature, write combined mask|semask as uint8.
// ----------------------------------------------------------------------------
__global__ __launch_bounds__(1024) void mask_prep_kernel(
    const unsigned char* __restrict__ m0,
    const unsigned char* __restrict__ m1)
{
    __shared__ int s_flags;
    const int t = threadIdx.x;
    if (t == 0) s_flags = 0;
    __syncthreads();

    int f1 = 0, f23 = 0;
    for (int i = t; i < BB * SS; i += 1024) {
        unsigned char a = (unsigned char)(m0[i] | m1[i]);
        int r = i & 3;
        if (a) {
            if (r == 1) f1 = 1;
            else if (r >= 2) f23 = 1;
        }
    }
    if (f1)  atomicOr(&s_flags, 1);
    if (f23) atomicOr(&s_flags, 2);
    __syncthreads();

    const int fl = s_flags;
    int code;
    if (fl & 1)      code = 0;  // uint8
    else if (fl & 2) code = 1;  // float32
    else             code = 2;  // int32

    for (int i = t; i < BB * SS; i += 1024) {
        unsigned char mm;
        if (code == 0) {
            mm = (unsigned char)((m0[i] != 0) | (m1[i] != 0));
        } else if (code == 1) {
            mm = (unsigned char)((((const float*)m0)[i] != 0.f) |
                                 (((const float*)m1)[i] != 0.f));
        } else {
            mm = (unsigned char)((((const int*)m0)[i] != 0) |
                                 (((const int*)m1)[i] != 0));
        }
        g_mask[i] = mm;
    }
}

// ----------------------------------------------------------------------------
// Tensor-core GEMM: C[M,N] = A[M,K] @ W[N,K]^T + bias[N]
// bf16x2 split (3-pass) mma.sync.m16n8k16, fp32 accumulate.
// Block tile 128x128x32, 256 threads (8 warps), warp tile 64x32.
// ----------------------------------------------------------------------------
#define SM_STRIDE 40  // bf16 elems per smem row (32 data + 8 pad, conflict-free)

__device__ __forceinline__ void mma16816(
    float& c0, float& c1, float& c2, float& c3,
    unsigned a0, unsigned a1, unsigned a2, unsigned a3,
    unsigned b0, unsigned b1)
{
    asm volatile(
        "mma.sync.aligned.m16n8k16.row.col.f32.bf16.bf16.f32 "
        "{%0,%1,%2,%3}, {%4,%5,%6,%7}, {%8,%9}, {%0,%1,%2,%3};\n"
        : "+f"(c0), "+f"(c1), "+f"(c2), "+f"(c3)
        : "r"(a0), "r"(a1), "r"(a2), "r"(a3), "r"(b0), "r"(b1));
}

__global__ __launch_bounds__(256) void gemm_mma_kernel(
    const float* __restrict__ A, const float* __restrict__ W,
    const float* __restrict__ bias, float* __restrict__ C,
    int M, int N, int K)
{
    __shared__ __align__(16) __nv_bfloat16 Ah[128][SM_STRIDE];
    __shared__ __align__(16) __nv_bfloat16 Al[128][SM_STRIDE];
    __shared__ __align__(16) __nv_bfloat16 Wh[128][SM_STRIDE];
    __shared__ __align__(16) __nv_bfloat16 Wl[128][SM_STRIDE];

    const int tid  = threadIdx.x;
    const int bm   = blockIdx.y * 128;
    const int bn   = blockIdx.x * 128;
    const int wid  = tid >> 5;
    const int lane = tid & 31;
    const int wm   = wid & 1;    // 0..1 -> 64-row half
    const int wn   = wid >> 1;   // 0..3 -> 32-col quarter
    const int g    = lane >> 2;  // group id 0..7
    const int tg   = lane & 3;   // thread in group

    float acc[4][4][4];
#pragma unroll
    for (int mt = 0; mt < 4; mt++)
#pragma unroll
        for (int nt = 0; nt < 4; nt++)
#pragma unroll
            for (int e = 0; e < 4; e++) acc[mt][nt][e] = 0.f;

    // staging map: idx = tid + i*256; row = idx/8; col4 = (idx%8)*4
    const int srow = tid >> 3;
    const int sc4  = (tid & 7) << 2;

    for (int k0 = 0; k0 < K; k0 += 32) {
        float4 av[4], wv[4];
#pragma unroll
        for (int i = 0; i < 4; i++) {
            int row = srow + i * 32;
            av[i] = *(const float4*)&A[(size_t)(bm + row) * K + k0 + sc4];
            wv[i] = *(const float4*)&W[(size_t)(bn + row) * K + k0 + sc4];
        }
        __syncthreads();  // previous iteration's fragment reads done
#pragma unroll
        for (int i = 0; i < 4; i++) {
            int row = srow + i * 32;
            float ax[4] = {av[i].x, av[i].y, av[i].z, av[i].w};
            float wx[4] = {wv[i].x, wv[i].y, wv[i].z, wv[i].w};
#pragma unroll
            for (int e = 0; e < 4; e++) {
                __nv_bfloat16 h = __float2bfloat16(ax[e]);
                __nv_bfloat16 l = __float2bfloat16(ax[e] - __bfloat162float(h));
                Ah[row][sc4 + e] = h;
                Al[row][sc4 + e] = l;
                h = __float2bfloat16(wx[e]);
                l = __float2bfloat16(wx[e] - __bfloat162float(h));
                Wh[row][sc4 + e] = h;
                Wl[row][sc4 + e] = l;
            }
        }
        __syncthreads();

#pragma unroll
        for (int ks = 0; ks < 32; ks += 16) {
            const int kc = ks + tg * 2;
            unsigned bh[4][2], bl[4][2];
#pragma unroll
            for (int nt = 0; nt < 4; nt++) {
                int n = wn * 32 + nt * 8 + g;
                bh[nt][0] = *(const unsigned*)&Wh[n][kc];
                bh[nt][1] = *(const unsigned*)&Wh[n][kc + 8];
                bl[nt][0] = *(const unsigned*)&Wl[n][kc];
                bl[nt][1] = *(const unsigned*)&Wl[n][kc + 8];
            }
#pragma unroll
            for (int mt = 0; mt < 4; mt++) {
                int r0 = wm * 64 + mt * 16 + g;
                unsigned ah0 = *(const unsigned*)&Ah[r0][kc];
                unsigned ah1 = *(const unsigned*)&Ah[r0 + 8][kc];
                unsigned ah2 = *(const unsigned*)&Ah[r0][kc + 8];
                unsigned ah3 = *(const unsigned*)&Ah[r0 + 8][kc + 8];
                unsigned al0 = *(const unsigned*)&Al[r0][kc];
                unsigned al1 = *(const unsigned*)&Al[r0 + 8][kc];
                unsigned al2 = *(const unsigned*)&Al[r0][kc + 8];
                unsigned al3 = *(const unsigned*)&Al[r0 + 8][kc + 8];
#pragma unroll
                for (int nt = 0; nt < 4; nt++) {
                    mma16816(acc[mt][nt][0], acc[mt][nt][1],
                             acc[mt][nt][2], acc[mt][nt][3],
                             ah0, ah1, ah2, ah3, bh[nt][0], bh[nt][1]);
                    mma16816(acc[mt][nt][0], acc[mt][nt][1],
                             acc[mt][nt][2], acc[mt][nt][3],
                             ah0, ah1, ah2, ah3, bl[nt][0], bl[nt][1]);
                    mma16816(acc[mt][nt][0], acc[mt][nt][1],
                             acc[mt][nt][2], acc[mt][nt][3],
                             al0, al1, al2, al3, bh[nt][0], bh[nt][1]);
                }
            }
        }
    }

    // Epilogue: bias add + direct STG (fragment c layout)
#pragma unroll
    for (int nt = 0; nt < 4; nt++) {
        int col = bn + wn * 32 + nt * 8 + tg * 2;
        float b0 = bias[col];
        float b1 = bias[col + 1];
#pragma unroll
        for (int mt = 0; mt < 4; mt++) {
            int row = bm + wm * 64 + mt * 16 + g;
            float* p0 = C + (size_t)row * N + col;
            float* p1 = C + (size_t)(row + 8) * N + col;
            p0[0] = acc[mt][nt][0] + b0;
            p0[1] = acc[mt][nt][1] + b1;
            p1[0] = acc[mt][nt][2] + b0;
            p1[1] = acc[mt][nt][3] + b1;
        }
    }
}

// ----------------------------------------------------------------------------
// Flash attention (fp32, online softmax) — unchanged from R4 (verified).
// ----------------------------------------------------------------------------
__global__ __launch_bounds__(128) void attn_kernel()
{
    const int t = threadIdx.x;
    const int q = blockIdx.x * 128 + t;
    const int h = blockIdx.y;
    const int b = blockIdx.z;
    const int hoff = h * DHH;

    __shared__ float Ks[64][64];
    __shared__ float Vs[64][64];
    __shared__ unsigned char smask[64];

    const float* qptr = g_Q + (size_t)(b * SS + q) * DD + hoff;
    float4 qv[16];
#pragma unroll
    for (int i = 0; i < 16; i++) qv[i] = *(const float4*)&qptr[i * 4];

    float4 ov[16];
#pragma unroll
    for (int i = 0; i < 16; i++) ov[i] = make_float4(0.f, 0.f, 0.f, 0.f);
    float mrun = -INFINITY;
    float lrun = 0.f;
    const float scale = 0.125f;  // 1/sqrt(64)

    for (int k0 = 0; k0 < SS; k0 += 64) {
        __syncthreads();
#pragma unroll
        for (int i = 0; i < 8; i++) {
            int f = t + i * 128;
            int j = f >> 4;
            int c = (f & 15) << 2;
            size_t gidx = (size_t)(b * SS + k0 + j) * DD + hoff + c;
            *(float4*)&Ks[j][c] = *(const float4*)&g_K[gidx];
            *(float4*)&Vs[j][c] = *(const float4*)&g_V[gidx];
        }
        if (t < 64) smask[t] = g_mask[b * SS + k0 + t];
        __syncthreads();

#pragma unroll 4
        for (int j = 0; j < 64; j++) {
            const float4* kr = (const float4*)Ks[j];
            float s = 0.f;
#pragma unroll
            for (int i = 0; i < 16; i++) {
                float4 kv = kr[i];
                s = fmaf(qv[i].x, kv.x, s);
                s = fmaf(qv[i].y, kv.y, s);
                s = fmaf(qv[i].z, kv.z, s);
                s = fmaf(qv[i].w, kv.w, s);
            }
            s *= scale;
            if (smask[j]) s = -1e9f;

            float p;
            if (s <= mrun) {
                p = __expf(s - mrun);
            } else {
                float corr = __expf(mrun - s);
                lrun *= corr;
#pragma unroll
                for (int i = 0; i < 16; i++) {
                    ov[i].x *= corr; ov[i].y *= corr;
                    ov[i].z *= corr; ov[i].w *= corr;
                }
                mrun = s;
                p = 1.f;
            }
            lrun += p;

            const float4* vr = (const float4*)Vs[j];
#pragma unroll
            for (int i = 0; i < 16; i++) {
                float4 vv = vr[i];
                ov[i].x = fmaf(p, vv.x, ov[i].x);
                ov[i].y = fmaf(p, vv.y, ov[i].y);
                ov[i].z = fmaf(p, vv.z, ov[i].z);
                ov[i].w = fmaf(p, vv.w, ov[i].w);
            }
        }
    }

    const float inv = 1.f / lrun;
    float* optr = g_C + (size_t)(b * SS + q) * DD + hoff;
#pragma unroll
    for (int i = 0; i < 16; i++) {
        float4 o = make_float4(ov[i].x * inv, ov[i].y * inv,
                               ov[i].z * inv, ov[i].w * inv);
        *(float4*)&optr[i * 4] = o;
    }
}

// ----------------------------------------------------------------------------
// Launch
// ----------------------------------------------------------------------------
extern "C" void kernel_launch(void* const* d_in, const int* in_sizes, int n_in,
                              void* d_out, int out_size)
{
    const float* v = (const float*)d_in[0];
    const float* k = (const float*)d_in[1];
    const float* q = (const float*)d_in[2];
    const unsigned char* mask   = (const unsigned char*)d_in[3];
    const unsigned char* semask = (const unsigned char*)d_in[4];
    const float* Wv = (const float*)d_in[5];
    const float* bv = (const float*)d_in[6];
    const float* Wk = (const float*)d_in[7];
    const float* bk = (const float*)d_in[8];
    const float* Wq = (const float*)d_in[9];
    const float* bq = (const float*)d_in[10];
    const float* Wm = (const float*)d_in[11];
    const float* bm = (const float*)d_in[12];

    static float* Qp = nullptr;
    static float* Kp = nullptr;
    static float* Vp = nullptr;
    static float* Cp = nullptr;
    if (!Qp) {
        cudaGetSymbolAddress((void**)&Qp, g_Q);
        cudaGetSymbolAddress((void**)&Kp, g_K);
        cudaGetSymbolAddress((void**)&Vp, g_V);
        cudaGetSymbolAddress((void**)&Cp, g_C);
    }

    mask_prep_kernel<<<1, 1024>>>(mask, semask);

    dim3 ggrid(DD / 128, MSZ / 128);  // (8, 32)
    gemm_mma_kernel<<<ggrid, 256>>>(v, Wv, bv, Vp, MSZ, DD, DD);
    gemm_mma_kernel<<<ggrid, 256>>>(k, Wk, bk, Kp, MSZ, DD, DD);
    gemm_mma_kernel<<<ggrid, 256>>>(q, Wq, bq, Qp, MSZ, DD, DD);

    dim3 agrid(SS / 128, HH, BB);     // (8, 16, 4)
    attn_kernel<<<agrid, 128>>>();

    gemm_mma_kernel<<<ggrid, 256>>>(Cp, Wm, bm, (float*)d_out, MSZ, DD, DD);
}

// round 8
// speedup vs baseline: 2.6203x; 1.8421x over previous
#include <cuda_runtime.h>
#include <cuda_bf16.h>
#include <math.h>

// Problem constants
#define BB 4
#define SS 1024
#define DD 1024
#define HH 16
#define DHH 64
#define MSZ (BB * SS)  // 4096 rows

// Scratch (no cudaMalloc allowed)
__device__ float g_Q[(size_t)MSZ * DD];
__device__ float g_K[(size_t)MSZ * DD];
__device__ float g_V[(size_t)MSZ * DD];
__device__ float g_C[(size_t)MSZ * DD];
__device__ unsigned char g_mask[BB * SS];

// ----------------------------------------------------------------------------
// Mask canonicalization (verified R4)
// ----------------------------------------------------------------------------
__global__ __launch_bounds__(1024) void mask_prep_kernel(
    const unsigned char* __restrict__ m0,
    const unsigned char* __restrict__ m1)
{
    __shared__ int s_flags;
    const int t = threadIdx.x;
    if (t == 0) s_flags = 0;
    __syncthreads();

    int f1 = 0, f23 = 0;
    for (int i = t; i < BB * SS; i += 1024) {
        unsigned char a = (unsigned char)(m0[i] | m1[i]);
        int r = i & 3;
        if (a) {
            if (r == 1) f1 = 1;
            else if (r >= 2) f23 = 1;
        }
    }
    if (f1)  atomicOr(&s_flags, 1);
    if (f23) atomicOr(&s_flags, 2);
    __syncthreads();

    const int fl = s_flags;
    int code;
    if (fl & 1)      code = 0;  // uint8
    else if (fl & 2) code = 1;  // float32
    else             code = 2;  // int32

    for (int i = t; i < BB * SS; i += 1024) {
        unsigned char mm;
        if (code == 0) {
            mm = (unsigned char)((m0[i] != 0) | (m1[i] != 0));
        } else if (code == 1) {
            mm = (unsigned char)((((const float*)m0)[i] != 0.f) |
                                 (((const float*)m1)[i] != 0.f));
        } else {
            mm = (unsigned char)((((const int*)m0)[i] != 0) |
                                 (((const int*)m1)[i] != 0));
        }
        g_mask[i] = mm;
    }
}

// ----------------------------------------------------------------------------
// Shared helpers
// ----------------------------------------------------------------------------
__device__ __forceinline__ void mma16816(
    float& c0, float& c1, float& c2, float& c3,
    unsigned a0, unsigned a1, unsigned a2, unsigned a3,
    unsigned b0, unsigned b1)
{
    asm volatile(
        "mma.sync.aligned.m16n8k16.row.col.f32.bf16.bf16.f32 "
        "{%0,%1,%2,%3}, {%4,%5,%6,%7}, {%8,%9}, {%0,%1,%2,%3};\n"
        : "+f"(c0), "+f"(c1), "+f"(c2), "+f"(c3)
        : "r"(a0), "r"(a1), "r"(a2), "r"(a3), "r"(b0), "r"(b1));
}

// Split two fp32 into packed bf16x2 hi and lo regs.
__device__ __forceinline__ void split2(float x, float y, unsigned& h, unsigned& l)
{
    __nv_bfloat16 hx = __float2bfloat16(x);
    __nv_bfloat16 hy = __float2bfloat16(y);
    __nv_bfloat16 lx = __float2bfloat16(x - __bfloat162float(hx));
    __nv_bfloat16 ly = __float2bfloat16(y - __bfloat162float(hy));
    __nv_bfloat162 hh; hh.x = hx; hh.y = hy;
    __nv_bfloat162 ll; ll.x = lx; ll.y = ly;
    h = *(unsigned*)&hh;
    l = *(unsigned*)&ll;
}

__device__ __forceinline__ void split1(float x, __nv_bfloat16& h, __nv_bfloat16& l)
{
    h = __float2bfloat16(x);
    l = __float2bfloat16(x - __bfloat162float(h));
}

// ----------------------------------------------------------------------------
// Tensor-core GEMM (verified R5): C[M,N] = A[M,K] @ W[N,K]^T + bias[N]
// ----------------------------------------------------------------------------
#define SM_STRIDE 40

__global__ __launch_bounds__(256) void gemm_mma_kernel(
    const float* __restrict__ A, const float* __restrict__ W,
    const float* __restrict__ bias, float* __restrict__ C,
    int M, int N, int K)
{
    __shared__ __align__(16) __nv_bfloat16 Ah[128][SM_STRIDE];
    __shared__ __align__(16) __nv_bfloat16 Al[128][SM_STRIDE];
    __shared__ __align__(16) __nv_bfloat16 Wh[128][SM_STRIDE];
    __shared__ __align__(16) __nv_bfloat16 Wl[128][SM_STRIDE];

    const int tid  = threadIdx.x;
    const int bm   = blockIdx.y * 128;
    const int bn   = blockIdx.x * 128;
    const int wid  = tid >> 5;
    const int lane = tid & 31;
    const int wm   = wid & 1;
    const int wn   = wid >> 1;
    const int g    = lane >> 2;
    const int tg   = lane & 3;

    float acc[4][4][4];
#pragma unroll
    for (int mt = 0; mt < 4; mt++)
#pragma unroll
        for (int nt = 0; nt < 4; nt++)
#pragma unroll
            for (int e = 0; e < 4; e++) acc[mt][nt][e] = 0.f;

    const int srow = tid >> 3;
    const int sc4  = (tid & 7) << 2;

    for (int k0 = 0; k0 < K; k0 += 32) {
        float4 av[4], wv[4];
#pragma unroll
        for (int i = 0; i < 4; i++) {
            int row = srow + i * 32;
            av[i] = *(const float4*)&A[(size_t)(bm + row) * K + k0 + sc4];
            wv[i] = *(const float4*)&W[(size_t)(bn + row) * K + k0 + sc4];
        }
        __syncthreads();
#pragma unroll
        for (int i = 0; i < 4; i++) {
            int row = srow + i * 32;
            float ax[4] = {av[i].x, av[i].y, av[i].z, av[i].w};
            float wx[4] = {wv[i].x, wv[i].y, wv[i].z, wv[i].w};
#pragma unroll
            for (int e = 0; e < 4; e++) {
                __nv_bfloat16 h, l;
                split1(ax[e], h, l);
                Ah[row][sc4 + e] = h;
                Al[row][sc4 + e] = l;
                split1(wx[e], h, l);
                Wh[row][sc4 + e] = h;
                Wl[row][sc4 + e] = l;
            }
        }
        __syncthreads();

#pragma unroll
        for (int ks = 0; ks < 32; ks += 16) {
            const int kc = ks + tg * 2;
            unsigned bh[4][2], bl[4][2];
#pragma unroll
            for (int nt = 0; nt < 4; nt++) {
                int n = wn * 32 + nt * 8 + g;
                bh[nt][0] = *(const unsigned*)&Wh[n][kc];
                bh[nt][1] = *(const unsigned*)&Wh[n][kc + 8];
                bl[nt][0] = *(const unsigned*)&Wl[n][kc];
                bl[nt][1] = *(const unsigned*)&Wl[n][kc + 8];
            }
#pragma unroll
            for (int mt = 0; mt < 4; mt++) {
                int r0 = wm * 64 + mt * 16 + g;
                unsigned ah0 = *(const unsigned*)&Ah[r0][kc];
                unsigned ah1 = *(const unsigned*)&Ah[r0 + 8][kc];
                unsigned ah2 = *(const unsigned*)&Ah[r0][kc + 8];
                unsigned ah3 = *(const unsigned*)&Ah[r0 + 8][kc + 8];
                unsigned al0 = *(const unsigned*)&Al[r0][kc];
                unsigned al1 = *(const unsigned*)&Al[r0 + 8][kc];
                unsigned al2 = *(const unsigned*)&Al[r0][kc + 8];
                unsigned al3 = *(const unsigned*)&Al[r0 + 8][kc + 8];
#pragma unroll
                for (int nt = 0; nt < 4; nt++) {
                    mma16816(acc[mt][nt][0], acc[mt][nt][1],
                             acc[mt][nt][2], acc[mt][nt][3],
                             ah0, ah1, ah2, ah3, bh[nt][0], bh[nt][1]);
                    mma16816(acc[mt][nt][0], acc[mt][nt][1],
                             acc[mt][nt][2], acc[mt][nt][3],
                             ah0, ah1, ah2, ah3, bl[nt][0], bl[nt][1]);
                    mma16816(acc[mt][nt][0], acc[mt][nt][1],
                             acc[mt][nt][2], acc[mt][nt][3],
                             al0, al1, al2, al3, bh[nt][0], bh[nt][1]);
                }
            }
        }
    }

#pragma unroll
    for (int nt = 0; nt < 4; nt++) {
        int col = bn + wn * 32 + nt * 8 + tg * 2;
        float b0 = bias[col];
        float b1 = bias[col + 1];
#pragma unroll
        for (int mt = 0; mt < 4; mt++) {
            int row = bm + wm * 64 + mt * 16 + g;
            float* p0 = C + (size_t)row * N + col;
            float* p1 = C + (size_t)(row + 8) * N + col;
            p0[0] = acc[mt][nt][0] + b0;
            p0[1] = acc[mt][nt][1] + b1;
            p1[0] = acc[mt][nt][2] + b0;
            p1[1] = acc[mt][nt][3] + b1;
        }
    }
}

// ----------------------------------------------------------------------------
// Tensor-core flash attention. Block = (b, h, 128 queries), 8 warps x 16 rows.
// 3-pass bf16x2 split for both QK^T and PV. Online softmax on C-fragments.
// ----------------------------------------------------------------------------
#define AST 72  // smem stride (64 + 8 pad): B-frag word idx = n*36 + k -> conflict-free

__global__ __launch_bounds__(256) void attn_mma_kernel()
{
    const int tid  = threadIdx.x;
    const int wid  = tid >> 5;
    const int lane = tid & 31;
    const int g    = lane >> 2;
    const int tg   = lane & 3;
    const int qb   = blockIdx.x * 128;
    const int h    = blockIdx.y;
    const int b    = blockIdx.z;
    const int hoff = h * DHH;
    const int qrow0 = qb + wid * 16;

    __shared__ __align__(16) __nv_bfloat16 Kh[64][AST], Kl[64][AST];
    __shared__ __align__(16) __nv_bfloat16 Vth[64][AST], Vtl[64][AST];  // [dim][key]
    __shared__ unsigned char smask[64];

    // ---- Load Q fragments for this warp (rows qrow0+g, qrow0+g+8) ----
    unsigned qh[4][4], ql[4][4];
    {
        const float* Q0 = g_Q + (size_t)(b * SS + qrow0 + g) * DD + hoff;
        const float* Q1 = g_Q + (size_t)(b * SS + qrow0 + g + 8) * DD + hoff;
#pragma unroll
        for (int ks = 0; ks < 4; ks++) {
            int d0 = ks * 16 + tg * 2;
            float2 f0 = *(const float2*)&Q0[d0];
            float2 f1 = *(const float2*)&Q1[d0];
            float2 f2 = *(const float2*)&Q0[d0 + 8];
            float2 f3 = *(const float2*)&Q1[d0 + 8];
            split2(f0.x, f0.y, qh[ks][0], ql[ks][0]);
            split2(f1.x, f1.y, qh[ks][1], ql[ks][1]);
            split2(f2.x, f2.y, qh[ks][2], ql[ks][2]);
            split2(f3.x, f3.y, qh[ks][3], ql[ks][3]);
        }
    }

    float out[8][4];
#pragma unroll
    for (int nt = 0; nt < 8; nt++)
#pragma unroll
        for (int e = 0; e < 4; e++) out[nt][e] = 0.f;
    float m0 = -INFINITY, m1 = -INFINITY;  // running max, rows g / g+8
    float l0 = 0.f, l1 = 0.f;              // per-thread partial row sums

    const int krow = tid >> 2;           // staging row 0..63
    const int kc4  = (tid & 3) * 16;     // staging dim base

    for (int kt = 0; kt < SS / 64; kt++) {
        // ---- Stage K (row-major) and V (transposed) as bf16 hi/lo ----
        float4 kv[4], vv[4];
        const float* Kg = g_K + (size_t)(b * SS + kt * 64 + krow) * DD + hoff + kc4;
        const float* Vg = g_V + (size_t)(b * SS + kt * 64 + krow) * DD + hoff + kc4;
#pragma unroll
        for (int i = 0; i < 4; i++) {
            kv[i] = *(const float4*)&Kg[i * 4];
            vv[i] = *(const float4*)&Vg[i * 4];
        }
        __syncthreads();  // previous tile's fragment reads done
#pragma unroll
        for (int i = 0; i < 4; i++) {
            float kx[4] = {kv[i].x, kv[i].y, kv[i].z, kv[i].w};
            float vx[4] = {vv[i].x, vv[i].y, vv[i].z, vv[i].w};
#pragma unroll
            for (int e = 0; e < 4; e++) {
                int d = kc4 + i * 4 + e;
                __nv_bfloat16 hh, ll;
                split1(kx[e], hh, ll);
                Kh[krow][d] = hh; Kl[krow][d] = ll;
                split1(vx[e], hh, ll);
                Vth[d][krow] = hh; Vtl[d][krow] = ll;  // transpose
            }
        }
        if (tid < 64) smask[tid] = g_mask[b * SS + kt * 64 + tid];
        __syncthreads();

        // ---- S = Q @ K^T (3-pass), scale, mask ----
        float sacc[8][4];
#pragma unroll
        for (int nt = 0; nt < 8; nt++) {
#pragma unroll
            for (int e = 0; e < 4; e++) sacc[nt][e] = 0.f;
            int n = nt * 8 + g;
#pragma unroll
            for (int ks = 0; ks < 4; ks++) {
                int kc = ks * 16 + tg * 2;
                unsigned bh0 = *(const unsigned*)&Kh[n][kc];
                unsigned bh1 = *(const unsigned*)&Kh[n][kc + 8];
                unsigned bl0 = *(const unsigned*)&Kl[n][kc];
                unsigned bl1 = *(const unsigned*)&Kl[n][kc + 8];
                mma16816(sacc[nt][0], sacc[nt][1], sacc[nt][2], sacc[nt][3],
                         qh[ks][0], qh[ks][1], qh[ks][2], qh[ks][3], bh0, bh1);
                mma16816(sacc[nt][0], sacc[nt][1], sacc[nt][2], sacc[nt][3],
                         qh[ks][0], qh[ks][1], qh[ks][2], qh[ks][3], bl0, bl1);
                mma16816(sacc[nt][0], sacc[nt][1], sacc[nt][2], sacc[nt][3],
                         ql[ks][0], ql[ks][1], ql[ks][2], ql[ks][3], bh0, bh1);
            }
        }

        float tmax0 = -INFINITY, tmax1 = -INFINITY;
#pragma unroll
        for (int nt = 0; nt < 8; nt++) {
            bool msk0 = smask[nt * 8 + tg * 2] != 0;
            bool msk1 = smask[nt * 8 + tg * 2 + 1] != 0;
            sacc[nt][0] = msk0 ? -1e9f : sacc[nt][0] * 0.125f;
            sacc[nt][1] = msk1 ? -1e9f : sacc[nt][1] * 0.125f;
            sacc[nt][2] = msk0 ? -1e9f : sacc[nt][2] * 0.125f;
            sacc[nt][3] = msk1 ? -1e9f : sacc[nt][3] * 0.125f;
            tmax0 = fmaxf(tmax0, fmaxf(sacc[nt][0], sacc[nt][1]));
            tmax1 = fmaxf(tmax1, fmaxf(sacc[nt][2], sacc[nt][3]));
        }
        // quad reduce (lanes g*4 .. g*4+3)
        tmax0 = fmaxf(tmax0, __shfl_xor_sync(0xffffffffu, tmax0, 1));
        tmax0 = fmaxf(tmax0, __shfl_xor_sync(0xffffffffu, tmax0, 2));
        tmax1 = fmaxf(tmax1, __shfl_xor_sync(0xffffffffu, tmax1, 1));
        tmax1 = fmaxf(tmax1, __shfl_xor_sync(0xffffffffu, tmax1, 2));

        float mn0 = fmaxf(m0, tmax0);
        float mn1 = fmaxf(m1, tmax1);
        float corr0 = __expf(m0 - mn0);  // exp(-inf)=0 on first tile
        float corr1 = __expf(m1 - mn1);
        m0 = mn0; m1 = mn1;
        l0 *= corr0; l1 *= corr1;
#pragma unroll
        for (int nt = 0; nt < 8; nt++) {
            out[nt][0] *= corr0; out[nt][1] *= corr0;
            out[nt][2] *= corr1; out[nt][3] *= corr1;
        }

        // ---- P = exp(S - m), pack hi/lo A-fragments (C-layout == A-layout) ----
        unsigned ph[4][4], pl[4][4];
#pragma unroll
        for (int ksp = 0; ksp < 4; ksp++) {
            float p00 = __expf(sacc[2 * ksp][0] - m0);
            float p01 = __expf(sacc[2 * ksp][1] - m0);
            float p10 = __expf(sacc[2 * ksp][2] - m1);
            float p11 = __expf(sacc[2 * ksp][3] - m1);
            float p20 = __expf(sacc[2 * ksp + 1][0] - m0);
            float p21 = __expf(sacc[2 * ksp + 1][1] - m0);
            float p30 = __expf(sacc[2 * ksp + 1][2] - m1);
            float p31 = __expf(sacc[2 * ksp + 1][3] - m1);
            l0 += p00 + p01 + p20 + p21;
            l1 += p10 + p11 + p30 + p31;
            split2(p00, p01, ph[ksp][0], pl[ksp][0]);
            split2(p10, p11, ph[ksp][1], pl[ksp][1]);
            split2(p20, p21, ph[ksp][2], pl[ksp][2]);
            split2(p30, p31, ph[ksp][3], pl[ksp][3]);
        }

        // ---- O += P @ V (3-pass), V^T B-fragments ----
#pragma unroll
        for (int nt = 0; nt < 8; nt++) {
            int n = nt * 8 + g;  // dim
#pragma unroll
            for (int ksp = 0; ksp < 4; ksp++) {
                int kc = ksp * 16 + tg * 2;  // key
                unsigned bh0 = *(const unsigned*)&Vth[n][kc];
                unsigned bh1 = *(const unsigned*)&Vth[n][kc + 8];
                unsigned bl0 = *(const unsigned*)&Vtl[n][kc];
                unsigned bl1 = *(const unsigned*)&Vtl[n][kc + 8];
                mma16816(out[nt][0], out[nt][1], out[nt][2], out[nt][3],
                         ph[ksp][0], ph[ksp][1], ph[ksp][2], ph[ksp][3], bh0, bh1);
                mma16816(out[nt][0], out[nt][1], out[nt][2], out[nt][3],
                         ph[ksp][0], ph[ksp][1], ph[ksp][2], ph[ksp][3], bl0, bl1);
                mma16816(out[nt][0], out[nt][1], out[nt][2], out[nt][3],
                         pl[ksp][0], pl[ksp][1], pl[ksp][2], pl[ksp][3], bh0, bh1);
            }
        }
    }

    // ---- Finalize: quad-reduce l, normalize, store ----
    l0 += __shfl_xor_sync(0xffffffffu, l0, 1);
    l0 += __shfl_xor_sync(0xffffffffu, l0, 2);
    l1 += __shfl_xor_sync(0xffffffffu, l1, 1);
    l1 += __shfl_xor_sync(0xffffffffu, l1, 2);
    const float inv0 = 1.f / l0;
    const float inv1 = 1.f / l1;

    float* O0 = g_C + (size_t)(b * SS + qrow0 + g) * DD + hoff;
    float* O1 = g_C + (size_t)(b * SS + qrow0 + g + 8) * DD + hoff;
#pragma unroll
    for (int nt = 0; nt < 8; nt++) {
        int d = nt * 8 + tg * 2;
        *(float2*)&O0[d] = make_float2(out[nt][0] * inv0, out[nt][1] * inv0);
        *(float2*)&O1[d] = make_float2(out[nt][2] * inv1, out[nt][3] * inv1);
    }
}

// ----------------------------------------------------------------------------
// Launch
// ----------------------------------------------------------------------------
extern "C" void kernel_launch(void* const* d_in, const int* in_sizes, int n_in,
                              void* d_out, int out_size)
{
    const float* v = (const float*)d_in[0];
    const float* k = (const float*)d_in[1];
    const float* q = (const float*)d_in[2];
    const unsigned char* mask   = (const unsigned char*)d_in[3];
    const unsigned char* semask = (const unsigned char*)d_in[4];
    const float* Wv = (const float*)d_in[5];
    const float* bv = (const float*)d_in[6];
    const float* Wk = (const float*)d_in[7];
    const float* bk = (const float*)d_in[8];
    const float* Wq = (const float*)d_in[9];
    const float* bq = (const float*)d_in[10];
    const float* Wm = (const float*)d_in[11];
    const float* bm = (const float*)d_in[12];

    static float* Qp = nullptr;
    static float* Kp = nullptr;
    static float* Vp = nullptr;
    static float* Cp = nullptr;
    if (!Qp) {
        cudaGetSymbolAddress((void**)&Qp, g_Q);
        cudaGetSymbolAddress((void**)&Kp, g_K);
        cudaGetSymbolAddress((void**)&Vp, g_V);
        cudaGetSymbolAddress((void**)&Cp, g_C);
    }

    mask_prep_kernel<<<1, 1024>>>(mask, semask);

    dim3 ggrid(DD / 128, MSZ / 128);  // (8, 32)
    gemm_mma_kernel<<<ggrid, 256>>>(v, Wv, bv, Vp, MSZ, DD, DD);
    gemm_mma_kernel<<<ggrid, 256>>>(k, Wk, bk, Kp, MSZ, DD, DD);
    gemm_mma_kernel<<<ggrid, 256>>>(q, Wq, bq, Qp, MSZ, DD, DD);

    dim3 agrid(SS / 128, HH, BB);     // (8, 16, 4)
    attn_mma_kernel<<<agrid, 256>>>();

    gemm_mma_kernel<<<ggrid, 256>>>(Cp, Wm, bm, (float*)d_out, MSZ, DD, DD);
}

// round 9
// speedup vs baseline: 2.7662x; 1.0557x over previous
#include <cuda_runtime.h>
#include <cuda_bf16.h>
#include <math.h>

// Problem constants
#define BB 4
#define SS 1024
#define DD 1024
#define HH 16
#define DHH 64
#define MSZ (BB * SS)  // 4096 rows

// Scratch (no cudaMalloc allowed)
__device__ float g_Q[(size_t)MSZ * DD];
__device__ float g_K[(size_t)MSZ * DD];
__device__ float g_V[(size_t)MSZ * DD];
__device__ float g_C[(size_t)MSZ * DD];
__device__ unsigned char g_mask[BB * SS];

// ----------------------------------------------------------------------------
// Mask canonicalization (verified R4)
// ----------------------------------------------------------------------------
__global__ __launch_bounds__(1024) void mask_prep_kernel(
    const unsigned char* __restrict__ m0,
    const unsigned char* __restrict__ m1)
{
    __shared__ int s_flags;
    const int t = threadIdx.x;
    if (t == 0) s_flags = 0;
    __syncthreads();

    int f1 = 0, f23 = 0;
    for (int i = t; i < BB * SS; i += 1024) {
        unsigned char a = (unsigned char)(m0[i] | m1[i]);
        int r = i & 3;
        if (a) {
            if (r == 1) f1 = 1;
            else if (r >= 2) f23 = 1;
        }
    }
    if (f1)  atomicOr(&s_flags, 1);
    if (f23) atomicOr(&s_flags, 2);
    __syncthreads();

    const int fl = s_flags;
    int code;
    if (fl & 1)      code = 0;  // uint8
    else if (fl & 2) code = 1;  // float32
    else             code = 2;  // int32

    for (int i = t; i < BB * SS; i += 1024) {
        unsigned char mm;
        if (code == 0) {
            mm = (unsigned char)((m0[i] != 0) | (m1[i] != 0));
        } else if (code == 1) {
            mm = (unsigned char)((((const float*)m0)[i] != 0.f) |
                                 (((const float*)m1)[i] != 0.f));
        } else {
            mm = (unsigned char)((((const int*)m0)[i] != 0) |
                                 (((const int*)m1)[i] != 0));
        }
        g_mask[i] = mm;
    }
}

// ----------------------------------------------------------------------------
// Shared helpers
// ----------------------------------------------------------------------------
__device__ __forceinline__ void mma16816(
    float& c0, float& c1, float& c2, float& c3,
    unsigned a0, unsigned a1, unsigned a2, unsigned a3,
    unsigned b0, unsigned b1)
{
    asm volatile(
        "mma.sync.aligned.m16n8k16.row.col.f32.bf16.bf16.f32 "
        "{%0,%1,%2,%3}, {%4,%5,%6,%7}, {%8,%9}, {%0,%1,%2,%3};\n"
        : "+f"(c0), "+f"(c1), "+f"(c2), "+f"(c3)
        : "r"(a0), "r"(a1), "r"(a2), "r"(a3), "r"(b0), "r"(b1));
}

__device__ __forceinline__ void ldsm4(unsigned addr, unsigned& r0, unsigned& r1,
                                      unsigned& r2, unsigned& r3)
{
    asm volatile(
        "ldmatrix.sync.aligned.m8n8.x4.shared.b16 {%0,%1,%2,%3}, [%4];"
        : "=r"(r0), "=r"(r1), "=r"(r2), "=r"(r3) : "r"(addr));
}

__device__ __forceinline__ void split2(float x, float y, unsigned& h, unsigned& l)
{
    __nv_bfloat16 hx = __float2bfloat16(x);
    __nv_bfloat16 hy = __float2bfloat16(y);
    __nv_bfloat16 lx = __float2bfloat16(x - __bfloat162float(hx));
    __nv_bfloat16 ly = __float2bfloat16(y - __bfloat162float(hy));
    __nv_bfloat162 hh; hh.x = hx; hh.y = hy;
    __nv_bfloat162 ll; ll.x = lx; ll.y = ly;
    h = *(unsigned*)&hh;
    l = *(unsigned*)&ll;
}

__device__ __forceinline__ void split1(float x, __nv_bfloat16& h, __nv_bfloat16& l)
{
    h = __float2bfloat16(x);
    l = __float2bfloat16(x - __bfloat162float(h));
}

// ----------------------------------------------------------------------------
// Tensor-core GEMM v2: double-buffered smem + ldmatrix fragment loads.
// C[M,N] = A[M,K] @ W[N,K]^T + bias[N]
// Block 128x128x32, 8 warps (warp tile 64x32), 3-pass bf16x2 split.
// ----------------------------------------------------------------------------
#define SM_STRIDE 40                         // bf16 per smem row (conflict-free)
#define GPLANE    (128 * SM_STRIDE)          // elems per plane
#define PLB       (GPLANE * 2)               // plane bytes (10240)
#define STAGEB    (4 * PLB)                  // stage bytes (40960)
#define GSMEM     (2 * STAGEB)               // total dynamic smem (81920)

__global__ __launch_bounds__(256, 2) void gemm_mma_kernel(
    const float* __restrict__ A, const float* __restrict__ W,
    const float* __restrict__ bias, float* __restrict__ C,
    int M, int N, int K)
{
    extern __shared__ __nv_bfloat16 smdyn[];

    const int tid  = threadIdx.x;
    const int bm   = blockIdx.y * 128;
    const int bn   = blockIdx.x * 128;
    const int wid  = tid >> 5;
    const int lane = tid & 31;
    const int wm   = wid & 1;
    const int wn   = wid >> 1;
    const int g    = lane >> 2;
    const int tg   = lane & 3;

    // ldmatrix lane mapping
    const int lm = lane >> 3;   // matrix index 0..3
    const int lt = lane & 7;    // row within matrix
    unsigned smem_u32;
    {
        unsigned long long p = __cvta_generic_to_shared(smdyn);
        smem_u32 = (unsigned)p;
    }
    // A frag addr (bytes, within Ah plane): row = wm*64 + (lm&1)*8 + lt, col = (lm>>1)*8
    const unsigned aoff = ((wm * 64 + ((lm & 1) << 3) + lt) * SM_STRIDE +
                           ((lm >> 1) << 3)) * 2;
    // B frag addr: row = wn*32 + (lm>>1)*8 + lt (+p*16), col = (lm&1)*8
    const unsigned boff = ((wn * 32 + ((lm >> 1) << 3) + lt) * SM_STRIDE +
                           ((lm & 1) << 3)) * 2;

    float acc[4][4][4];
#pragma unroll
    for (int mt = 0; mt < 4; mt++)
#pragma unroll
        for (int nt = 0; nt < 4; nt++)
#pragma unroll
            for (int e = 0; e < 4; e++) acc[mt][nt][e] = 0.f;

    // staging map: 1024 float4 per tile per matrix; 4 per thread
    const int srow = tid >> 3;
    const int sc4  = (tid & 7) << 2;

    float4 av[4], wv[4];
#pragma unroll
    for (int i = 0; i < 4; i++) {
        int row = srow + i * 32;
        av[i] = *(const float4*)&A[(size_t)(bm + row) * K + sc4];
        wv[i] = *(const float4*)&W[(size_t)(bn + row) * K + sc4];
    }
    // store stage 0
    {
        __nv_bfloat16* Ahp = smdyn;
        __nv_bfloat16* Alp = smdyn + GPLANE;
        __nv_bfloat16* Whp = smdyn + 2 * GPLANE;
        __nv_bfloat16* Wlp = smdyn + 3 * GPLANE;
#pragma unroll
        for (int i = 0; i < 4; i++) {
            int row = srow + i * 32;
            float ax[4] = {av[i].x, av[i].y, av[i].z, av[i].w};
            float wx[4] = {wv[i].x, wv[i].y, wv[i].z, wv[i].w};
#pragma unroll
            for (int e = 0; e < 4; e++) {
                __nv_bfloat16 h, l;
                split1(ax[e], h, l);
                Ahp[row * SM_STRIDE + sc4 + e] = h;
                Alp[row * SM_STRIDE + sc4 + e] = l;
                split1(wx[e], h, l);
                Whp[row * SM_STRIDE + sc4 + e] = h;
                Wlp[row * SM_STRIDE + sc4 + e] = l;
            }
        }
    }
    __syncthreads();

    const int NT = K / 32;
    for (int kt = 0; kt < NT; kt++) {
        const int cur = kt & 1;
        const unsigned sbase = smem_u32 + (unsigned)cur * STAGEB;

        // prefetch next tile into registers
        if (kt + 1 < NT) {
            int k0 = (kt + 1) * 32;
#pragma unroll
            for (int i = 0; i < 4; i++) {
                int row = srow + i * 32;
                av[i] = *(const float4*)&A[(size_t)(bm + row) * K + k0 + sc4];
                wv[i] = *(const float4*)&W[(size_t)(bn + row) * K + k0 + sc4];
            }
        }

        // compute on stage cur
#pragma unroll
        for (int ks = 0; ks < 32; ks += 16) {
            unsigned bh[4][2], bl[4][2];
#pragma unroll
            for (int p = 0; p < 2; p++) {
                unsigned ad = sbase + 2 * PLB + boff +
                              (unsigned)(p * 16 * SM_STRIDE + ks) * 2;
                unsigned r0, r1, r2, r3;
                ldsm4(ad, r0, r1, r2, r3);
                bh[2 * p][0] = r0; bh[2 * p][1] = r1;
                bh[2 * p + 1][0] = r2; bh[2 * p + 1][1] = r3;
                ldsm4(ad + PLB, r0, r1, r2, r3);
                bl[2 * p][0] = r0; bl[2 * p][1] = r1;
                bl[2 * p + 1][0] = r2; bl[2 * p + 1][1] = r3;
            }
#pragma unroll
            for (int mt = 0; mt < 4; mt++) {
                unsigned ad = sbase + aoff +
                              (unsigned)(mt * 16 * SM_STRIDE + ks) * 2;
                unsigned ah0, ah1, ah2, ah3, al0, al1, al2, al3;
                ldsm4(ad, ah0, ah1, ah2, ah3);
                ldsm4(ad + PLB, al0, al1, al2, al3);
#pragma unroll
                for (int nt = 0; nt < 4; nt++) {
                    mma16816(acc[mt][nt][0], acc[mt][nt][1],
                             acc[mt][nt][2], acc[mt][nt][3],
                             ah0, ah1, ah2, ah3, bh[nt][0], bh[nt][1]);
                    mma16816(acc[mt][nt][0], acc[mt][nt][1],
                             acc[mt][nt][2], acc[mt][nt][3],
                             ah0, ah1, ah2, ah3, bl[nt][0], bl[nt][1]);
                    mma16816(acc[mt][nt][0], acc[mt][nt][1],
                             acc[mt][nt][2], acc[mt][nt][3],
                             al0, al1, al2, al3, bh[nt][0], bh[nt][1]);
                }
            }
        }

        // store next tile to the other stage
        if (kt + 1 < NT) {
            int nxt = cur ^ 1;
            __nv_bfloat16* Ahp = smdyn + nxt * 4 * GPLANE;
            __nv_bfloat16* Alp = Ahp + GPLANE;
            __nv_bfloat16* Whp = Ahp + 2 * GPLANE;
            __nv_bfloat16* Wlp = Ahp + 3 * GPLANE;
#pragma unroll
            for (int i = 0; i < 4; i++) {
                int row = srow + i * 32;
                float ax[4] = {av[i].x, av[i].y, av[i].z, av[i].w};
                float wx[4] = {wv[i].x, wv[i].y, wv[i].z, wv[i].w};
#pragma unroll
                for (int e = 0; e < 4; e++) {
                    __nv_bfloat16 h, l;
                    split1(ax[e], h, l);
                    Ahp[row * SM_STRIDE + sc4 + e] = h;
                    Alp[row * SM_STRIDE + sc4 + e] = l;
                    split1(wx[e], h, l);
                    Whp[row * SM_STRIDE + sc4 + e] = h;
                    Wlp[row * SM_STRIDE + sc4 + e] = l;
                }
            }
        }
        __syncthreads();
    }

    // Epilogue: bias add + direct STG
#pragma unroll
    for (int nt = 0; nt < 4; nt++) {
        int col = bn + wn * 32 + nt * 8 + tg * 2;
        float b0 = bias[col];
        float b1 = bias[col + 1];
#pragma unroll
        for (int mt = 0; mt < 4; mt++) {
            int row = bm + wm * 64 + mt * 16 + g;
            float* p0 = C + (size_t)row * N + col;
            float* p1 = C + (size_t)(row + 8) * N + col;
            p0[0] = acc[mt][nt][0] + b0;
            p0[1] = acc[mt][nt][1] + b1;
            p1[0] = acc[mt][nt][2] + b0;
            p1[1] = acc[mt][nt][3] + b1;
        }
    }
}

// ----------------------------------------------------------------------------
// Tensor-core flash attention (verified R8) — unchanged.
// ----------------------------------------------------------------------------
#define AST 72

__global__ __launch_bounds__(256) void attn_mma_kernel()
{
    const int tid  = threadIdx.x;
    const int wid  = tid >> 5;
    const int lane = tid & 31;
    const int g    = lane >> 2;
    const int tg   = lane & 3;
    const int qb   = blockIdx.x * 128;
    const int h    = blockIdx.y;
    const int b    = blockIdx.z;
    const int hoff = h * DHH;
    const int qrow0 = qb + wid * 16;

    __shared__ __align__(16) __nv_bfloat16 Kh[64][AST], Kl[64][AST];
    __shared__ __align__(16) __nv_bfloat16 Vth[64][AST], Vtl[64][AST];
    __shared__ unsigned char smask[64];

    unsigned qh[4][4], ql[4][4];
    {
        const float* Q0 = g_Q + (size_t)(b * SS + qrow0 + g) * DD + hoff;
        const float* Q1 = g_Q + (size_t)(b * SS + qrow0 + g + 8) * DD + hoff;
#pragma unroll
        for (int ks = 0; ks < 4; ks++) {
            int d0 = ks * 16 + tg * 2;
            float2 f0 = *(const float2*)&Q0[d0];
            float2 f1 = *(const float2*)&Q1[d0];
            float2 f2 = *(const float2*)&Q0[d0 + 8];
            float2 f3 = *(const float2*)&Q1[d0 + 8];
            split2(f0.x, f0.y, qh[ks][0], ql[ks][0]);
            split2(f1.x, f1.y, qh[ks][1], ql[ks][1]);
            split2(f2.x, f2.y, qh[ks][2], ql[ks][2]);
            split2(f3.x, f3.y, qh[ks][3], ql[ks][3]);
        }
    }

    float out[8][4];
#pragma unroll
    for (int nt = 0; nt < 8; nt++)
#pragma unroll
        for (int e = 0; e < 4; e++) out[nt][e] = 0.f;
    float m0 = -INFINITY, m1 = -INFINITY;
    float l0 = 0.f, l1 = 0.f;

    const int krow = tid >> 2;
    const int kc4  = (tid & 3) * 16;

    for (int kt = 0; kt < SS / 64; kt++) {
        float4 kv[4], vv[4];
        const float* Kg = g_K + (size_t)(b * SS + kt * 64 + krow) * DD + hoff + kc4;
        const float* Vg = g_V + (size_t)(b * SS + kt * 64 + krow) * DD + hoff + kc4;
#pragma unroll
        for (int i = 0; i < 4; i++) {
            kv[i] = *(const float4*)&Kg[i * 4];
            vv[i] = *(const float4*)&Vg[i * 4];
        }
        __syncthreads();
#pragma unroll
        for (int i = 0; i < 4; i++) {
            float kx[4] = {kv[i].x, kv[i].y, kv[i].z, kv[i].w};
            float vx[4] = {vv[i].x, vv[i].y, vv[i].z, vv[i].w};
#pragma unroll
            for (int e = 0; e < 4; e++) {
                int d = kc4 + i * 4 + e;
                __nv_bfloat16 hh, ll;
                split1(kx[e], hh, ll);
                Kh[krow][d] = hh; Kl[krow][d] = ll;
                split1(vx[e], hh, ll);
                Vth[d][krow] = hh; Vtl[d][krow] = ll;
            }
        }
        if (tid < 64) smask[tid] = g_mask[b * SS + kt * 64 + tid];
        __syncthreads();

        float sacc[8][4];
#pragma unroll
        for (int nt = 0; nt < 8; nt++) {
#pragma unroll
            for (int e = 0; e < 4; e++) sacc[nt][e] = 0.f;
            int n = nt * 8 + g;
#pragma unroll
            for (int ks = 0; ks < 4; ks++) {
                int kc = ks * 16 + tg * 2;
                unsigned bh0 = *(const unsigned*)&Kh[n][kc];
                unsigned bh1 = *(const unsigned*)&Kh[n][kc + 8];
                unsigned bl0 = *(const unsigned*)&Kl[n][kc];
                unsigned bl1 = *(const unsigned*)&Kl[n][kc + 8];
                mma16816(sacc[nt][0], sacc[nt][1], sacc[nt][2], sacc[nt][3],
                         qh[ks][0], qh[ks][1], qh[ks][2], qh[ks][3], bh0, bh1);
                mma16816(sacc[nt][0], sacc[nt][1], sacc[nt][2], sacc[nt][3],
                         qh[ks][0], qh[ks][1], qh[ks][2], qh[ks][3], bl0, bl1);
                mma16816(sacc[nt][0], sacc[nt][1], sacc[nt][2], sacc[nt][3],
                         ql[ks][0], ql[ks][1], ql[ks][2], ql[ks][3], bh0, bh1);
            }
        }

        float tmax0 = -INFINITY, tmax1 = -INFINITY;
#pragma unroll
        for (int nt = 0; nt < 8; nt++) {
            bool msk0 = smask[nt * 8 + tg * 2] != 0;
            bool msk1 = smask[nt * 8 + tg * 2 + 1] != 0;
            sacc[nt][0] = msk0 ? -1e9f : sacc[nt][0] * 0.125f;
            sacc[nt][1] = msk1 ? -1e9f : sacc[nt][1] * 0.125f;
            sacc[nt][2] = msk0 ? -1e9f : sacc[nt][2] * 0.125f;
            sacc[nt][3] = msk1 ? -1e9f : sacc[nt][3] * 0.125f;
            tmax0 = fmaxf(tmax0, fmaxf(sacc[nt][0], sacc[nt][1]));
            tmax1 = fmaxf(tmax1, fmaxf(sacc[nt][2], sacc[nt][3]));
        }
        tmax0 = fmaxf(tmax0, __shfl_xor_sync(0xffffffffu, tmax0, 1));
        tmax0 = fmaxf(tmax0, __shfl_xor_sync(0xffffffffu, tmax0, 2));
        tmax1 = fmaxf(tmax1, __shfl_xor_sync(0xffffffffu, tmax1, 1));
        tmax1 = fmaxf(tmax1, __shfl_xor_sync(0xffffffffu, tmax1, 2));

        float mn0 = fmaxf(m0, tmax0);
        float mn1 = fmaxf(m1, tmax1);
        float corr0 = __expf(m0 - mn0);
        float corr1 = __expf(m1 - mn1);
        m0 = mn0; m1 = mn1;
        l0 *= corr0; l1 *= corr1;
#pragma unroll
        for (int nt = 0; nt < 8; nt++) {
            out[nt][0] *= corr0; out[nt][1] *= corr0;
            out[nt][2] *= corr1; out[nt][3] *= corr1;
        }

        unsigned ph[4][4], pl[4][4];
#pragma unroll
        for (int ksp = 0; ksp < 4; ksp++) {
            float p00 = __expf(sacc[2 * ksp][0] - m0);
            float p01 = __expf(sacc[2 * ksp][1] - m0);
            float p10 = __expf(sacc[2 * ksp][2] - m1);
            float p11 = __expf(sacc[2 * ksp][3] - m1);
            float p20 = __expf(sacc[2 * ksp + 1][0] - m0);
            float p21 = __expf(sacc[2 * ksp + 1][1] - m0);
            float p30 = __expf(sacc[2 * ksp + 1][2] - m1);
            float p31 = __expf(sacc[2 * ksp + 1][3] - m1);
            l0 += p00 + p01 + p20 + p21;
            l1 += p10 + p11 + p30 + p31;
            split2(p00, p01, ph[ksp][0], pl[ksp][0]);
            split2(p10, p11, ph[ksp][1], pl[ksp][1]);
            split2(p20, p21, ph[ksp][2], pl[ksp][2]);
            split2(p30, p31, ph[ksp][3], pl[ksp][3]);
        }

#pragma unroll
        for (int nt = 0; nt < 8; nt++) {
            int n = nt * 8 + g;
#pragma unroll
            for (int ksp = 0; ksp < 4; ksp++) {
                int kc = ksp * 16 + tg * 2;
                unsigned bh0 = *(const unsigned*)&Vth[n][kc];
                unsigned bh1 = *(const unsigned*)&Vth[n][kc + 8];
                unsigned bl0 = *(const unsigned*)&Vtl[n][kc];
                unsigned bl1 = *(const unsigned*)&Vtl[n][kc + 8];
                mma16816(out[nt][0], out[nt][1], out[nt][2], out[nt][3],
                         ph[ksp][0], ph[ksp][1], ph[ksp][2], ph[ksp][3], bh0, bh1);
                mma16816(out[nt][0], out[nt][1], out[nt][2], out[nt][3],
                         ph[ksp][0], ph[ksp][1], ph[ksp][2], ph[ksp][3], bl0, bl1);
                mma16816(out[nt][0], out[nt][1], out[nt][2], out[nt][3],
                         pl[ksp][0], pl[ksp][1], pl[ksp][2], pl[ksp][3], bh0, bh1);
            }
        }
    }

    l0 += __shfl_xor_sync(0xffffffffu, l0, 1);
    l0 += __shfl_xor_sync(0xffffffffu, l0, 2);
    l1 += __shfl_xor_sync(0xffffffffu, l1, 1);
    l1 += __shfl_xor_sync(0xffffffffu, l1, 2);
    const float inv0 = 1.f / l0;
    const float inv1 = 1.f / l1;

    float* O0 = g_C + (size_t)(b * SS + qrow0 + g) * DD + hoff;
    float* O1 = g_C + (size_t)(b * SS + qrow0 + g + 8) * DD + hoff;
#pragma unroll
    for (int nt = 0; nt < 8; nt++) {
        int d = nt * 8 + tg * 2;
        *(float2*)&O0[d] = make_float2(out[nt][0] * inv0, out[nt][1] * inv0);
        *(float2*)&O1[d] = make_float2(out[nt][2] * inv1, out[nt][3] * inv1);
    }
}

// ----------------------------------------------------------------------------
// Launch
// ----------------------------------------------------------------------------
extern "C" void kernel_launch(void* const* d_in, const int* in_sizes, int n_in,
                              void* d_out, int out_size)
{
    const float* v = (const float*)d_in[0];
    const float* k = (const float*)d_in[1];
    const float* q = (const float*)d_in[2];
    const unsigned char* mask   = (const unsigned char*)d_in[3];
    const unsigned char* semask = (const unsigned char*)d_in[4];
    const float* Wv = (const float*)d_in[5];
    const float* bv = (const float*)d_in[6];
    const float* Wk = (const float*)d_in[7];
    const float* bk = (const float*)d_in[8];
    const float* Wq = (const float*)d_in[9];
    const float* bq = (const float*)d_in[10];
    const float* Wm = (const float*)d_in[11];
    const float* bm = (const float*)d_in[12];

    static float* Qp = nullptr;
    static float* Kp = nullptr;
    static float* Vp = nullptr;
    static float* Cp = nullptr;
    if (!Qp) {
        cudaGetSymbolAddress((void**)&Qp, g_Q);
        cudaGetSymbolAddress((void**)&Kp, g_K);
        cudaGetSymbolAddress((void**)&Vp, g_V);
        cudaGetSymbolAddress((void**)&Cp, g_C);
        cudaFuncSetAttribute(gemm_mma_kernel,
                             cudaFuncAttributeMaxDynamicSharedMemorySize, GSMEM);
    }

    mask_prep_kernel<<<1, 1024>>>(mask, semask);

    dim3 ggrid(DD / 128, MSZ / 128);  // (8, 32)
    gemm_mma_kernel<<<ggrid, 256, GSMEM>>>(v, Wv, bv, Vp, MSZ, DD, DD);
    gemm_mma_kernel<<<ggrid, 256, GSMEM>>>(k, Wk, bk, Kp, MSZ, DD, DD);
    gemm_mma_kernel<<<ggrid, 256, GSMEM>>>(q, Wq, bq, Qp, MSZ, DD, DD);

    dim3 agrid(SS / 128, HH, BB);     // (8, 16, 4)
    attn_mma_kernel<<<agrid, 256>>>();

    gemm_mma_kernel<<<ggrid, 256, GSMEM>>>(Cp, Wm, bm, (float*)d_out, MSZ, DD, DD);
}